// round 2
// baseline (speedup 1.0000x reference)
#include <cuda_runtime.h>

#define HH 800
#define WW 800
#define PP 8
#define NPTS 200000
#define DIM 8
#define HID 256
#define NPIX (HH*WW)
#define NSLOT (NPIX*PP)
#define Z_THRESH 0.2f

// -------- persistent scratch (no allocs allowed) --------
__device__ float4 g_acc4[NPTS];               // sum dir.x, dir.y, dir.z, cos
__device__ float2 g_acc2[NPTS];               // count, valid_count
__device__ unsigned long long g_zkey[NPTS];   // (first_idx << 32) | float_bits(z)
__device__ float g_feat[NPTS * DIM];          // MLP output per point

// -------- kernel 1: reset accumulators --------
__global__ void k_init() {
    int i = blockIdx.x * blockDim.x + threadIdx.x;
    if (i < NPTS) {
        g_acc4[i] = make_float4(0.f, 0.f, 0.f, 0.f);
        g_acc2[i] = make_float2(0.f, 0.f);
        g_zkey[i] = ~0ULL;
    }
}

// -------- kernel 2: segment scatter (3 atomics per slot) --------
__global__ void __launch_bounds__(256) k_scatter(
    const float* __restrict__ zbufs,
    const float* __restrict__ ray,
    const int* __restrict__ idbufs)
{
    int pix = blockIdx.x * blockDim.x + threadIdx.x;
    if (pix >= NPIX) return;

    const float4* zb4 = (const float4*)zbufs;
    const int4*   id4 = (const int4*)idbufs;
    float4 za = zb4[pix * 2 + 0];
    float4 zb = zb4[pix * 2 + 1];
    int4   ia = id4[pix * 2 + 0];
    int4   ib = id4[pix * 2 + 1];

    float dx = __ldg(ray + pix * 7 + 3);
    float dy = __ldg(ray + pix * 7 + 4);
    float dz = __ldg(ray + pix * 7 + 5);
    float cs = __ldg(ray + pix * 7 + 6);
    float4 v4 = make_float4(dx, dy, dz, cs);

    int   ids[8] = {ia.x, ia.y, ia.z, ia.w, ib.x, ib.y, ib.z, ib.w};
    float zs[8]  = {za.x, za.y, za.z, za.w, zb.x, zb.y, zb.z, zb.w};

    unsigned long long ibase = (unsigned long long)pix * PP;
#pragma unroll
    for (int p = 0; p < 8; p++) {
        int id = ids[p];
        atomicAdd(&g_acc4[id], v4);
        atomicAdd(&g_acc2[id], make_float2(1.0f, zs[p] > Z_THRESH ? 1.0f : 0.0f));
        unsigned long long key = ((ibase + p) << 32)
                               | (unsigned long long)__float_as_uint(zs[p]);
        atomicMin(&g_zkey[id], key);
    }
}

// -------- kernel 3: per-point MLP (6 -> 256 relu -> 8) --------
__global__ void __launch_bounds__(256) k_mlp(
    const float* __restrict__ ray,
    const float* __restrict__ W1,
    const float* __restrict__ b1,
    const float* __restrict__ W2,
    const float* __restrict__ b2)
{
    __shared__ float sw1[HID * 8];   // [j] : W1[0..5][j], b1[j], pad
    __shared__ float sw2[HID * 8];   // [j] : W2[j][0..7]

    int tid = threadIdx.x;
    for (int j = tid; j < HID; j += blockDim.x) {
#pragma unroll
        for (int k = 0; k < 6; k++) sw1[j * 8 + k] = W1[k * HID + j];
        sw1[j * 8 + 6] = b1[j];
        sw1[j * 8 + 7] = 0.f;
#pragma unroll
        for (int d = 0; d < 8; d++) sw2[j * 8 + d] = W2[j * 8 + d];
    }
    __syncthreads();

    int pt = blockIdx.x * blockDim.x + tid;
    if (pt >= NPTS) return;

    float4 a4 = g_acc4[pt];
    float2 a2 = g_acc2[pt];
    float cnt = a2.x;
    bool valid = (a2.y > 0.0f) && (cnt > 0.0f);

    float f[8];
    if (!valid) {
#pragma unroll
        for (int d = 0; d < 8; d++) f[d] = 0.f;
    } else {
        float safe = fmaxf(cnt, 1.0f);
        float dux = a4.x / safe, duy = a4.y / safe, duz = a4.z / safe;
        float cosm = a4.w / safe;
        unsigned long long key = g_zkey[pt];
        float zf = __uint_as_float((unsigned)(key & 0xFFFFFFFFULL));

        float o0 = __ldg(ray + 0), o1 = __ldg(ray + 1), o2 = __ldg(ray + 2);
        float x0 = o0 + (zf * dux) / cosm;
        float x1 = o1 + (zf * duy) / cosm;
        float x2 = o2 + (zf * duz) / cosm;
        float x3 = dux, x4 = duy, x5 = duz;

#pragma unroll
        for (int d = 0; d < 8; d++) f[d] = __ldg(b2 + d);

        const float4* w1v = (const float4*)sw1;
        const float4* w2v = (const float4*)sw2;
#pragma unroll 4
        for (int j = 0; j < HID; j++) {
            float4 wa = w1v[2 * j];
            float4 wb = w1v[2 * j + 1];
            float h = wb.z;                       // b1[j]
            h = fmaf(x0, wa.x, h);
            h = fmaf(x1, wa.y, h);
            h = fmaf(x2, wa.z, h);
            h = fmaf(x3, wa.w, h);
            h = fmaf(x4, wb.x, h);
            h = fmaf(x5, wb.y, h);
            h = fmaxf(h, 0.0f);
            float4 va = w2v[2 * j];
            float4 vb = w2v[2 * j + 1];
            f[0] = fmaf(h, va.x, f[0]);
            f[1] = fmaf(h, va.y, f[1]);
            f[2] = fmaf(h, va.z, f[2]);
            f[3] = fmaf(h, va.w, f[3]);
            f[4] = fmaf(h, vb.x, f[4]);
            f[5] = fmaf(h, vb.y, f[5]);
            f[6] = fmaf(h, vb.z, f[6]);
            f[7] = fmaf(h, vb.w, f[7]);
        }
    }

    float4* fo = (float4*)(g_feat + (size_t)pt * 8);
    fo[0] = make_float4(f[0], f[1], f[2], f[3]);
    fo[1] = make_float4(f[4], f[5], f[6], f[7]);
}

// -------- kernel 4: gather + channel transpose to [1,64,H,W] --------
// block = 256 threads = 32 pixels (one row segment) x 8 slots.
__global__ void __launch_bounds__(256) k_out(
    const int* __restrict__ idbufs,
    float* __restrict__ out)
{
    __shared__ float tile[64 * 33];   // [channel][w_local], padded

    int t = threadIdx.x;              // 0..255
    int h = blockIdx.y;
    int w0 = blockIdx.x * 32;
    int wl = t >> 3;                  // 0..31
    int p  = t & 7;

    int base = (h * WW + w0) * PP;
    int id = idbufs[base + t];        // fully coalesced

    const float4* fp = (const float4*)(g_feat + (size_t)id * 8);
    float4 fa = fp[0], fb = fp[1];

    int cb = p * 8;
    tile[(cb + 0) * 33 + wl] = fa.x;
    tile[(cb + 1) * 33 + wl] = fa.y;
    tile[(cb + 2) * 33 + wl] = fa.z;
    tile[(cb + 3) * 33 + wl] = fa.w;
    tile[(cb + 4) * 33 + wl] = fb.x;
    tile[(cb + 5) * 33 + wl] = fb.y;
    tile[(cb + 6) * 33 + wl] = fb.z;
    tile[(cb + 7) * 33 + wl] = fb.w;
    __syncthreads();

    int lane = t & 31;
    int cw = t >> 5;                  // 0..7
#pragma unroll
    for (int r = 0; r < 8; r++) {
        int c = r * 8 + cw;           // 0..63
        out[(size_t)c * NPIX + h * WW + w0 + lane] = tile[c * 33 + lane];
    }
}

extern "C" void kernel_launch(void* const* d_in, const int* in_sizes, int n_in,
                              void* d_out, int out_size)
{
    const float* zbufs = (const float*)d_in[0];
    const float* ray   = (const float*)d_in[1];
    const float* W1    = (const float*)d_in[2];
    const float* b1    = (const float*)d_in[3];
    const float* W2    = (const float*)d_in[4];
    const float* b2    = (const float*)d_in[5];
    const int*   idb   = (const int*)d_in[6];
    float* out = (float*)d_out;

    k_init<<<(NPTS + 255) / 256, 256>>>();
    k_scatter<<<(NPIX + 255) / 256, 256>>>(zbufs, ray, idb);
    k_mlp<<<(NPTS + 255) / 256, 256>>>(ray, W1, b1, W2, b2);
    k_out<<<dim3(WW / 32, HH), 256>>>(idb, out);
}

// round 4
// speedup vs baseline: 1.1611x; 1.1611x over previous
#include <cuda_runtime.h>

#define HH 800
#define WW 800
#define PP 8
#define NPTS 200000
#define DIM 8
#define HID 256
#define NPIX (HH*WW)
#define NSLOT (NPIX*PP)
#define Z_THRESH 0.2f

// -------- persistent scratch (no allocs allowed) --------
__device__ float4 g_acc4[NPTS];      // sum dir.x, dir.y, dir.z, cos
__device__ unsigned g_cnt[NPTS];     // count | (valid_count << 16)
__device__ unsigned g_minidx[NPTS];  // min flat slot index
__device__ float g_feat[NPTS * DIM]; // MLP output per point

// -------- kernel 1: reset accumulators --------
__global__ void k_init() {
    int i = blockIdx.x * blockDim.x + threadIdx.x;
    if (i < NPTS) {
        g_acc4[i] = make_float4(0.f, 0.f, 0.f, 0.f);
        g_cnt[i] = 0u;
        g_minidx[i] = 0xFFFFFFFFu;
    }
}

// -------- kernel 2: segment scatter (3 atomics, 6 L2 words per slot) --------
__global__ void __launch_bounds__(256) k_scatter(
    const float* __restrict__ zbufs,
    const float* __restrict__ ray,
    const int* __restrict__ idbufs)
{
    int pix = blockIdx.x * blockDim.x + threadIdx.x;
    if (pix >= NPIX) return;

    const float4* zb4 = (const float4*)zbufs;
    const int4*   id4 = (const int4*)idbufs;
    float4 za = zb4[pix * 2 + 0];
    float4 zb = zb4[pix * 2 + 1];
    int4   ia = id4[pix * 2 + 0];
    int4   ib = id4[pix * 2 + 1];

    float dx = __ldg(ray + pix * 7 + 3);
    float dy = __ldg(ray + pix * 7 + 4);
    float dz = __ldg(ray + pix * 7 + 5);
    float cs = __ldg(ray + pix * 7 + 6);
    float4 v4 = make_float4(dx, dy, dz, cs);

    int   ids[8] = {ia.x, ia.y, ia.z, ia.w, ib.x, ib.y, ib.z, ib.w};
    float zs[8]  = {za.x, za.y, za.z, za.w, zb.x, zb.y, zb.z, zb.w};

    unsigned ibase = (unsigned)pix * PP;
#pragma unroll
    for (int p = 0; p < 8; p++) {
        int id = ids[p];
        atomicAdd(&g_acc4[id], v4);
        atomicAdd(&g_cnt[id], 1u + (zs[p] > Z_THRESH ? 0x10000u : 0u));
        atomicMin(&g_minidx[id], ibase + p);
    }
}

// -------- kernel 3: per-point MLP (6 -> 256 relu -> 8), 4 points/thread ----
__global__ void __launch_bounds__(128) k_mlp(
    const float* __restrict__ zbufs,
    const float* __restrict__ ray,
    const float* __restrict__ W1,
    const float* __restrict__ b1,
    const float* __restrict__ W2,
    const float* __restrict__ b2)
{
    __shared__ float sw1[HID * 8];   // [j] : W1[0..5][j], b1[j], pad
    __shared__ float sw2[HID * 8];   // [j] : W2[j][0..7]

    int tid = threadIdx.x;
    for (int j = tid; j < HID; j += 128) {
#pragma unroll
        for (int k = 0; k < 6; k++) sw1[j * 8 + k] = W1[k * HID + j];
        sw1[j * 8 + 6] = b1[j];
        sw1[j * 8 + 7] = 0.f;
#pragma unroll
        for (int d = 0; d < 8; d++) sw2[j * 8 + d] = W2[j * 8 + d];
    }
    __syncthreads();

    float o0 = __ldg(ray + 0), o1 = __ldg(ray + 1), o2 = __ldg(ray + 2);

    int base = blockIdx.x * 512 + tid;   // 4 points strided by 128
    float x[4][6];
    float f[4][8];
    bool  ok[4];

#pragma unroll
    for (int k = 0; k < 4; k++) {
        int pt = base + k * 128;
        bool inb = pt < NPTS;
        int ptc = inb ? pt : 0;

        float4 a4 = g_acc4[ptc];
        unsigned cw = g_cnt[ptc];
        unsigned cnt = cw & 0xFFFFu;
        unsigned vld = cw >> 16;
        unsigned mi = g_minidx[ptc];
        mi = mi < (NSLOT - 1) ? mi : (NSLOT - 1);
        float zf = __ldg(zbufs + mi);

        ok[k] = inb && (cnt > 0u) && (vld > 0u);
        float safe = fmaxf((float)cnt, 1.0f);
        float inv = 1.0f / safe;
        float dux = a4.x * inv, duy = a4.y * inv, duz = a4.z * inv;
        float cosm = a4.w * inv;
        float zc = ok[k] ? (zf / cosm) : 0.0f;

        x[k][0] = ok[k] ? o0 + zc * dux : 0.f;
        x[k][1] = ok[k] ? o1 + zc * duy : 0.f;
        x[k][2] = ok[k] ? o2 + zc * duz : 0.f;
        x[k][3] = ok[k] ? dux : 0.f;
        x[k][4] = ok[k] ? duy : 0.f;
        x[k][5] = ok[k] ? duz : 0.f;
#pragma unroll
        for (int d = 0; d < 8; d++) f[k][d] = __ldg(b2 + d);
    }

    const float4* w1v = (const float4*)sw1;
    const float4* w2v = (const float4*)sw2;
#pragma unroll 2
    for (int j = 0; j < HID; j++) {
        float4 wa = w1v[2 * j];
        float4 wb = w1v[2 * j + 1];
        float4 va = w2v[2 * j];
        float4 vb = w2v[2 * j + 1];
#pragma unroll
        for (int k = 0; k < 4; k++) {
            float h = wb.z;                       // b1[j]
            h = fmaf(x[k][0], wa.x, h);
            h = fmaf(x[k][1], wa.y, h);
            h = fmaf(x[k][2], wa.z, h);
            h = fmaf(x[k][3], wa.w, h);
            h = fmaf(x[k][4], wb.x, h);
            h = fmaf(x[k][5], wb.y, h);
            h = fmaxf(h, 0.0f);
            f[k][0] = fmaf(h, va.x, f[k][0]);
            f[k][1] = fmaf(h, va.y, f[k][1]);
            f[k][2] = fmaf(h, va.z, f[k][2]);
            f[k][3] = fmaf(h, va.w, f[k][3]);
            f[k][4] = fmaf(h, vb.x, f[k][4]);
            f[k][5] = fmaf(h, vb.y, f[k][5]);
            f[k][6] = fmaf(h, vb.z, f[k][6]);
            f[k][7] = fmaf(h, vb.w, f[k][7]);
        }
    }

#pragma unroll
    for (int k = 0; k < 4; k++) {
        int pt = base + k * 128;
        if (pt >= NPTS) continue;
        float4* fo = (float4*)(g_feat + (size_t)pt * 8);
        if (ok[k]) {
            fo[0] = make_float4(f[k][0], f[k][1], f[k][2], f[k][3]);
            fo[1] = make_float4(f[k][4], f[k][5], f[k][6], f[k][7]);
        } else {
            fo[0] = make_float4(0.f, 0.f, 0.f, 0.f);
            fo[1] = make_float4(0.f, 0.f, 0.f, 0.f);
        }
    }
}

// -------- kernel 4: gather, direct coalesced plane writes (no smem) -------
// block = 256 = 8 warps; warp w owns p=w for 32 consecutive pixels.
__global__ void __launch_bounds__(256) k_out(
    const int* __restrict__ idbufs,
    float* __restrict__ out)
{
    int t = threadIdx.x;
    int p = t >> 5;                   // 0..7
    int lane = t & 31;
    int pix = blockIdx.y * WW + blockIdx.x * 32 + lane;

    int id = __ldg(idbufs + pix * PP + p);

    const float4* fp = (const float4*)(g_feat + (size_t)id * 8);
    float4 fa = fp[0], fb = fp[1];

    float* o = out + (size_t)(p * 8) * NPIX + pix;
    o[0 * NPIX] = fa.x;
    o[1 * NPIX] = fa.y;
    o[2 * NPIX] = fa.z;
    o[3 * NPIX] = fa.w;
    o[4 * NPIX] = fb.x;
    o[5 * NPIX] = fb.y;
    o[6 * NPIX] = fb.z;
    o[7 * NPIX] = fb.w;
}

extern "C" void kernel_launch(void* const* d_in, const int* in_sizes, int n_in,
                              void* d_out, int out_size)
{
    const float* zbufs = (const float*)d_in[0];
    const float* ray   = (const float*)d_in[1];
    const float* W1    = (const float*)d_in[2];
    const float* b1    = (const float*)d_in[3];
    const float* W2    = (const float*)d_in[4];
    const float* b2    = (const float*)d_in[5];
    const int*   idb   = (const int*)d_in[6];
    float* out = (float*)d_out;

    k_init<<<(NPTS + 255) / 256, 256>>>();
    k_scatter<<<(NPIX + 255) / 256, 256>>>(zbufs, ray, idb);
    k_mlp<<<(NPTS + 511) / 512, 128>>>(zbufs, ray, W1, b1, W2, b2);
    k_out<<<dim3(WW / 32, HH), 256>>>(idb, out);
}